// round 16
// baseline (speedup 1.0000x reference)
#include <cuda_runtime.h>
#include <cstdint>

#define B 2048
#define N 65536
#define F 128
#define TOPK 3
#define NLAB 10
#define SPLITS 9
#define CHUNKS (N / 128)  // 512 chunks of 128 candidates

// ---------------- device scratch (no allocations allowed) ----------------
__device__ float g_xfT[F * B];        // (x * features) transposed: [f][b], 1 MB
__device__ float g_trainT[F * N];     // train transposed: [f][n], 32 MB
__device__ float g_left[B];           // sum(x^2) per query
__device__ float g_right[N];          // sum((feat*train)^2) per candidate
__device__ float g_pval[B * SPLITS * TOPK];
__device__ int   g_pidx[B * SPLITS * TOPK];

// ---------------- helpers ----------------
__device__ __forceinline__ void cp_async16(uint32_t saddr, const void* gaddr) {
    asm volatile("cp.async.cg.shared.global [%0], [%1], 16;\n" :: "r"(saddr), "l"(gaddr));
}

__device__ __forceinline__ bool better(float v, int i, float V, int I) {
    // jax.lax.top_k order: larger value first; ties -> lower index first
    return (v > V) || (v == V && i < I);
}

__device__ __forceinline__ void insert_cmp(float* bv, int* bi, float v, int i) {
    if (!better(v, i, bv[2], bi[2])) return;
    if (better(v, i, bv[0], bi[0])) {
        bv[2] = bv[1]; bi[2] = bi[1];
        bv[1] = bv[0]; bi[1] = bi[0];
        bv[0] = v;     bi[0] = i;
    } else if (better(v, i, bv[1], bi[1])) {
        bv[2] = bv[1]; bi[2] = bi[1];
        bv[1] = v;     bi[1] = i;
    } else {
        bv[2] = v;     bi[2] = i;
    }
}

// ---------------- prep: left[b], xfT ----------------
__global__ void prep_x_kernel(const float* __restrict__ x, const float* __restrict__ feats) {
    int warp = (blockIdx.x * blockDim.x + threadIdx.x) >> 5;
    int lane = threadIdx.x & 31;
    if (warp >= B) return;
    float4 xv = *(const float4*)&x[warp * F + lane * 4];
    float4 fv = *(const float4*)&feats[lane * 4];
    float s = xv.x * xv.x + xv.y * xv.y + xv.z * xv.z + xv.w * xv.w;
    #pragma unroll
    for (int o = 16; o; o >>= 1) s += __shfl_xor_sync(0xffffffffu, s, o);
    if (lane == 0) g_left[warp] = s;
    int f0 = lane * 4;
    g_xfT[(f0 + 0) * B + warp] = xv.x * fv.x;
    g_xfT[(f0 + 1) * B + warp] = xv.y * fv.y;
    g_xfT[(f0 + 2) * B + warp] = xv.z * fv.z;
    g_xfT[(f0 + 3) * B + warp] = xv.w * fv.w;
}

// ---------------- prep: right[n] ----------------
__global__ void prep_right_kernel(const float* __restrict__ train, const float* __restrict__ feats) {
    int warp = (blockIdx.x * blockDim.x + threadIdx.x) >> 5;
    int lane = threadIdx.x & 31;
    if (warp >= N) return;
    float4 tv = *(const float4*)&train[warp * F + lane * 4];
    float4 fv = *(const float4*)&feats[lane * 4];
    float wx = tv.x * fv.x, wy = tv.y * fv.y, wz = tv.z * fv.z, ww = tv.w * fv.w;
    float s = wx * wx + wy * wy + wz * wz + ww * ww;
    #pragma unroll
    for (int o = 16; o; o >>= 1) s += __shfl_xor_sync(0xffffffffu, s, o);
    if (lane == 0) g_right[warp] = s;
}

// ---------------- prep: trainT = (feats * train) transposed ----------------
__global__ void transpose_kernel(const float* __restrict__ train, const float* __restrict__ feats) {
    __shared__ float tile[32][33];
    int n0 = blockIdx.x * 32, f0 = blockIdx.y * 32;
    int tx = threadIdx.x, ty = threadIdx.y;  // block (32, 8)
    float fscale = feats[f0 + tx];
    #pragma unroll
    for (int r = 0; r < 32; r += 8)
        tile[ty + r][tx] = train[(n0 + ty + r) * F + f0 + tx] * fscale;
    __syncthreads();
    #pragma unroll
    for (int r = 0; r < 32; r += 8)
        g_trainT[(f0 + ty + r) * N + n0 + tx] = tile[tx][ty + r];
}

// ---------------- main fused GEMM + top-3 ----------------
// grid (B/128, SPLITS) = 144 blocks, 512 threads (16 warps -> 4/SMSP), 192 KB smem
// Xs [k][q] 128x128 (64 KB); Ws [2][k][c] double-buffered (128 KB)
// Per-thread: 4 queries x 8 candidates. f32x2 lanes = CANDIDATE PAIRS (natural
// u64 W loads); the 4 X query scalars are lane-duplicated (4 dups/kk).
// kk-loop uses explicit register double-buffering: iteration kk+1's smem loads
// are issued before iteration kk's FMAs so the 29-cyc LDS latency is hidden
// structurally (R9 showed ptxas could not pipeline at regs=127).
extern "C" __global__ void __launch_bounds__(512, 1) knn_main_kernel() {
    extern __shared__ float smem[];
    float* Xs = smem;
    float* Ws = smem + 128 * 128;

    const int tid = threadIdx.x;
    const int tx = tid & 15;    // candidate group (8 cands)
    const int qg = tid >> 4;    // query group (4 queries), 32 groups
    const int qbase = blockIdx.x * 128;
    const int c0 = (blockIdx.y * CHUNKS) / SPLITS;
    const int c1 = ((blockIdx.y + 1) * CHUNKS) / SPLITS;

    uint32_t sX = (uint32_t)__cvta_generic_to_shared(Xs);
    uint32_t sW = (uint32_t)__cvta_generic_to_shared(Ws);

    // Fill X tile + first W tile: 4096 float4s each, 512 threads -> 8 each.
    #pragma unroll
    for (int i = 0; i < 8; i++) {
        int idx = tid + i * 512;
        int row = idx >> 5, col = (idx & 31) * 4;
        cp_async16(sX + (row * 128 + col) * 4, &g_xfT[row * B + qbase + col]);
    }
    #pragma unroll
    for (int i = 0; i < 8; i++) {
        int idx = tid + i * 512;
        int row = idx >> 5, col = (idx & 31) * 4;
        cp_async16(sW + (row * 128 + col) * 4, &g_trainT[row * N + c0 * 128 + col]);
    }
    asm volatile("cp.async.commit_group;\n");

    float lq[4];
    #pragma unroll
    for (int i = 0; i < 4; i++) lq[i] = g_left[qbase + qg * 4 + i];

    float tv[4][3];
    int   ti[4][3];
    #pragma unroll
    for (int i = 0; i < 4; i++)
        #pragma unroll
        for (int k = 0; k < 3; k++) { tv[i][k] = -3.4e38f; ti[i][k] = 0x7fffffff; }

    int cur = 0;
    for (int c = c0; c < c1; ++c) {
        if (c + 1 < c1) {
            uint32_t sWn = sW + (cur ^ 1) * 128 * 128 * 4;
            #pragma unroll
            for (int i = 0; i < 8; i++) {
                int idx = tid + i * 512;
                int row = idx >> 5, col = (idx & 31) * 4;
                cp_async16(sWn + (row * 128 + col) * 4,
                           &g_trainT[row * N + (c + 1) * 128 + col]);
            }
            asm volatile("cp.async.commit_group;\n");
            asm volatile("cp.async.wait_group 1;\n");
        } else {
            asm volatile("cp.async.wait_group 0;\n");
        }
        __syncthreads();

        const float* Wc = Ws + cur * 128 * 128;
        // acc[q*4 + cp]: lanes = (cand 2cp, cand 2cp+1), q = query 0..3
        unsigned long long acc[16];
        #pragma unroll
        for (int i = 0; i < 16; i++) acc[i] = 0ull;

        // explicit kk pipeline: preload kk=0
        float4      xv_c = *(const float4*)&Xs[0 * 128 + qg * 4];
        ulonglong2  wa_c = *(const ulonglong2*)&Wc[0 * 128 + tx * 8];
        ulonglong2  wb_c = *(const ulonglong2*)&Wc[0 * 128 + tx * 8 + 4];

        #pragma unroll 4
        for (int kk = 0; kk < 128; ++kk) {
            float4     xv_n;
            ulonglong2 wa_n, wb_n;
            if (kk + 1 < 128) {
                xv_n = *(const float4*)&Xs[(kk + 1) * 128 + qg * 4];
                wa_n = *(const ulonglong2*)&Wc[(kk + 1) * 128 + tx * 8];
                wb_n = *(const ulonglong2*)&Wc[(kk + 1) * 128 + tx * 8 + 4];
            }
            float xs[4] = {xv_c.x, xv_c.y, xv_c.z, xv_c.w};
            unsigned long long w01 = wa_c.x, w23 = wa_c.y, w45 = wb_c.x, w67 = wb_c.y;
            #pragma unroll
            for (int q = 0; q < 4; q++) {
                unsigned long long xd;
                asm("mov.b64 %0, {%1, %1};" : "=l"(xd) : "r"(__float_as_uint(xs[q])));
                asm("fma.rn.f32x2 %0, %1, %2, %0;" : "+l"(acc[q * 4 + 0]) : "l"(xd), "l"(w01));
                asm("fma.rn.f32x2 %0, %1, %2, %0;" : "+l"(acc[q * 4 + 1]) : "l"(xd), "l"(w23));
                asm("fma.rn.f32x2 %0, %1, %2, %0;" : "+l"(acc[q * 4 + 2]) : "l"(xd), "l"(w45));
                asm("fma.rn.f32x2 %0, %1, %2, %0;" : "+l"(acc[q * 4 + 3]) : "l"(xd), "l"(w67));
            }
            xv_c = xv_n; wa_c = wa_n; wb_c = wb_n;
        }

        // epilogue: distance + per-thread top-3 over 4 queries x 8 candidates
        const int cb = c * 128 + tx * 8;
        float rr[8];
        #pragma unroll
        for (int j = 0; j < 8; j++) rr[j] = g_right[cb + j];
        #pragma unroll
        for (int q = 0; q < 4; q++) {
            float L = lq[q];
            #pragma unroll
            for (int cp = 0; cp < 4; cp++) {
                unsigned int u0, u1;
                asm("mov.b64 {%0, %1}, %2;" : "=r"(u0), "=r"(u1) : "l"(acc[q * 4 + cp]));
                float d0 = __uint_as_float(u0);   // candidate cb + 2cp
                float d1 = __uint_as_float(u1);   // candidate cb + 2cp + 1
                float s0 = __fsqrt_rn(L + rr[cp * 2]);
                float s1 = __fsqrt_rn(L + rr[cp * 2 + 1]);
                float v0c = 2.0f * d0 - s0;       // = -distance
                float v1c = 2.0f * d1 - s1;
                int n0 = cb + cp * 2;
                insert_cmp(tv[q], ti[q], v0c, n0);
                insert_cmp(tv[q], ti[q], v1c, n0 + 1);
            }
        }
        __syncthreads();   // all reads of buffer `cur` done before it is refilled
        cur ^= 1;
    }

    // block-level merge across the 16 candidate-group threads (reuse smem)
    float* sV = smem;                       // 128 q * 16 tx * 3 = 6144 floats (24 KB)
    int*   sI = (int*)(smem + 128 * 48);    // 24 KB
    #pragma unroll
    for (int i = 0; i < 4; i++) {
        int q = qg * 4 + i;
        #pragma unroll
        for (int k = 0; k < 3; k++) {
            sV[(q * 16 + tx) * 3 + k] = tv[i][k];
            sI[(q * 16 + tx) * 3 + k] = ti[i][k];
        }
    }
    __syncthreads();
    if (tid < 128) {
        float bv[3] = {-3.4e38f, -3.4e38f, -3.4e38f};
        int   bi[3] = {0x7fffffff, 0x7fffffff, 0x7fffffff};
        for (int e = 0; e < 48; e++)
            insert_cmp(bv, bi, sV[tid * 48 + e], sI[tid * 48 + e]);
        int b = qbase + tid;
        int base = (b * SPLITS + blockIdx.y) * 3;
        #pragma unroll
        for (int k = 0; k < 3; k++) { g_pval[base + k] = bv[k]; g_pidx[base + k] = bi[k]; }
    }
}

// ---------------- finalize: merge splits, labels, one-hot ----------------
__global__ void finalize_kernel(const int* __restrict__ labels, float* __restrict__ out) {
    int b = blockIdx.x * blockDim.x + threadIdx.x;
    if (b >= B) return;
    float bv[3] = {-3.4e38f, -3.4e38f, -3.4e38f};
    int   bi[3] = {0x7fffffff, 0x7fffffff, 0x7fffffff};
    #pragma unroll
    for (int e = 0; e < SPLITS * 3; e++)
        insert_cmp(bv, bi, g_pval[b * SPLITS * 3 + e], g_pidx[b * SPLITS * 3 + e]);

    int l0 = labels[bi[0]], l1 = labels[bi[1]], l2 = labels[bi[2]];
    int lab = (l0 + l1 + l2) / TOPK;  // labels >= 0 -> trunc == floor

    // output layout (float32, reference tuple order):
    // [0, B*10)            one_hot
    // [B*10, B*13)         values
    // [B*13, B*16)         indices
    // [B*16, B*19)         labels
    #pragma unroll
    for (int c = 0; c < NLAB; c++) out[b * NLAB + c] = (c == lab) ? 1.0f : 0.0f;
    float* ov = out + B * NLAB;
    float* oi = out + B * (NLAB + 3);
    float* ol = out + B * (NLAB + 6);
    ov[b * 3 + 0] = bv[0]; ov[b * 3 + 1] = bv[1]; ov[b * 3 + 2] = bv[2];
    oi[b * 3 + 0] = (float)bi[0]; oi[b * 3 + 1] = (float)bi[1]; oi[b * 3 + 2] = (float)bi[2];
    ol[b * 3 + 0] = (float)l0; ol[b * 3 + 1] = (float)l1; ol[b * 3 + 2] = (float)l2;
}

// ---------------- launch ----------------
extern "C" void kernel_launch(void* const* d_in, const int* in_sizes, int n_in,
                              void* d_out, int out_size) {
    const float* x      = (const float*)d_in[0];
    const float* train  = (const float*)d_in[1];
    const int*   labels = (const int*)d_in[2];
    const float* feats  = (const float*)d_in[3];
    float* out = (float*)d_out;

    cudaFuncSetAttribute(knn_main_kernel, cudaFuncAttributeMaxDynamicSharedMemorySize, 196608);

    prep_x_kernel<<<B / 8, 256>>>(x, feats);
    prep_right_kernel<<<N / 8, 256>>>(train, feats);
    transpose_kernel<<<dim3(N / 32, F / 32), dim3(32, 8)>>>(train, feats);
    knn_main_kernel<<<dim3(B / 128, SPLITS), 512, 196608>>>();
    finalize_kernel<<<(B + 255) / 256, 256>>>(labels, out);
}